// round 7
// baseline (speedup 1.0000x reference)
#include <cuda_runtime.h>
#include <cuda_bf16.h>
#include <math_constants.h>

// Problem constants
#define T_TOKENS 4096
#define HIDDEN   2048
#define N_EXP    8
#define H4       (HIDDEN / 4)          // 512 float4 per hidden row

// Output layout (floats), outputs concatenated:
//   [0, 32768)                router_scores [E, T]
//   [32768, +67108864)        router_indices [E*T, H] (value = t, as float)
//   [67141632, 67174400)      router_probs [E*T, 1] == scores flattened
#define SCORES_OFF 0
#define IDX_OFF    (N_EXP * T_TOKENS)                       // 32768
#define IDX_ELEMS  ((size_t)N_EXP * T_TOKENS * HIDDEN)      // 67108864
#define PROBS_OFF  (IDX_OFF + IDX_ELEMS)                    // 67141632

// ---------------------------------------------------------------------------
// Kernel 1: logits + top-2 + sigmoid scatter.
// 1024 blocks x 128 threads, 1 token per warp (4096 warps total).
// Small CTAs -> ~7 CTAs/SM, ~27 warps/SM: fine-grained load balance and
// enough MLP to be hs-DRAM-bound (R6: 256 fat blocks = 1.73 CTA/SM,
// imbalance-bound at 11.6us).
// ---------------------------------------------------------------------------
__global__ __launch_bounds__(128, 6)
void router_logits_kernel(const float* __restrict__ hs,
                          const float* __restrict__ wr,
                          float* __restrict__ out) {
    const int warp = threadIdx.x >> 5;
    const int lane = threadIdx.x & 31;
    const int t = blockIdx.x * 4 + warp;          // one token per warp

    const float4* __restrict__ hs4 = (const float4*)hs + (size_t)t * H4;
    const float4* __restrict__ w4  = (const float4*)wr;

    float acc[N_EXP];
#pragma unroll
    for (int e = 0; e < N_EXP; e++) acc[e] = 0.f;

#pragma unroll 4
    for (int ii = 0; ii < H4 / 32; ii++) {        // 16 iterations
        const int i = ii * 32 + lane;
        const float4 x = hs4[i];
#pragma unroll
        for (int e = 0; e < N_EXP; e++) {
            const float4 wv = __ldg(&w4[e * H4 + i]);
            acc[e] += x.x * wv.x + x.y * wv.y + x.z * wv.z + x.w * wv.w;
        }
    }

    // butterfly warp reduction: every lane ends with full sums
#pragma unroll
    for (int e = 0; e < N_EXP; e++)
#pragma unroll
        for (int o = 16; o > 0; o >>= 1)
            acc[e] += __shfl_xor_sync(0xffffffffu, acc[e], o);

    if (lane == 0) {
        // top-1
        float b1 = -CUDART_INF_F; int i1 = 0;
#pragma unroll
        for (int e = 0; e < N_EXP; e++)
            if (acc[e] > b1) { b1 = acc[e]; i1 = e; }
        // top-2 (excluding i1)
        float b2 = -CUDART_INF_F; int i2 = -1;
#pragma unroll
        for (int e = 0; e < N_EXP; e++)
            if (e != i1 && acc[e] > b2) { b2 = acc[e]; i2 = e; }

        const float s1 = 1.f / (1.f + __expf(-b1));
        const float s2 = 1.f / (1.f + __expf(-b2));
#pragma unroll
        for (int e = 0; e < N_EXP; e++) {
            const float s = (e == i1) ? s1 : ((e == i2) ? s2 : 0.f);
            out[SCORES_OFF + (size_t)e * T_TOKENS + t] = s;
            out[PROBS_OFF  + (size_t)e * T_TOKENS + t] = s;
        }
    }
}

// ---------------------------------------------------------------------------
// Kernel 2: fill router_indices region (268 MB pattern write).
// 8192 blocks x 256 threads x 8 float4/thread. Measured 37.6us @ 70% DRAM
// (write-stream ceiling ~5.5 TB/s; occupancy-insensitive).
// ---------------------------------------------------------------------------
#define FILL_F4_PER_THREAD 8
#define FILL_BLOCKS (16777216 / (256 * FILL_F4_PER_THREAD))   // 8192

__global__ __launch_bounds__(256)
void fill_indices_kernel(float4* __restrict__ out4) {
    const size_t base = (size_t)blockIdx.x * (256 * FILL_F4_PER_THREAD) + threadIdx.x;
#pragma unroll
    for (int j = 0; j < FILL_F4_PER_THREAD; j++) {
        const size_t i = base + (size_t)j * 256;
        const float v = (float)((i >> 9) & (T_TOKENS - 1));
        __stcs(&out4[i], make_float4(v, v, v, v));
    }
}

extern "C" void kernel_launch(void* const* d_in, const int* in_sizes, int n_in,
                              void* d_out, int out_size) {
    const float* hs = (const float*)d_in[0];  // [T, H] fp32
    const float* wr = (const float*)d_in[1];  // [E, H] fp32
    float* out = (float*)d_out;

    router_logits_kernel<<<1024, 128>>>(hs, wr, out);
    fill_indices_kernel<<<FILL_BLOCKS, 256>>>((float4*)(out + IDX_OFF));
}

// round 8
// speedup vs baseline: 1.2353x; 1.2353x over previous
#include <cuda_runtime.h>
#include <cuda_bf16.h>
#include <math_constants.h>

// Problem constants
#define T_TOKENS 4096
#define HIDDEN   2048
#define N_EXP    8
#define H4       (HIDDEN / 4)          // 512 float4 per hidden row

// Output layout (floats), outputs concatenated:
//   [0, 32768)                router_scores [E, T]
//   [32768, +67108864)        router_indices [E*T, H] (value = t, as float)
//   [67141632, 67174400)      router_probs [E*T, 1] == scores flattened
#define SCORES_OFF 0
#define IDX_OFF    (N_EXP * T_TOKENS)                       // 32768
#define IDX_ELEMS  ((size_t)N_EXP * T_TOKENS * HIDDEN)      // 67108864
#define PROBS_OFF  (IDX_OFF + IDX_ELEMS)                    // 67141632

// Fused grid, blockDim = 128:
//   ids [0, 512)        logits blocks: 4 warps x 2 tokens = 8 tokens/block
//   ids [512, 16896)    fill blocks: 128 thr x 8 float4 = 1024 f4/block
#define LOGITS_BLOCKS 512
#define TPW 2
#define FILL_F4_PER_THREAD 8
#define FILL_F4_PER_BLOCK (128 * FILL_F4_PER_THREAD)        // 1024
#define FILL_BLOCKS (16777216 / FILL_F4_PER_BLOCK)          // 16384
#define GRID_BLOCKS (LOGITS_BLOCKS + FILL_BLOCKS)           // 16896

__global__ __launch_bounds__(128, 6)
void router_fused_kernel(const float* __restrict__ hs,
                         const float* __restrict__ wr,
                         float* __restrict__ out) {
    const unsigned bid = blockIdx.x;

    if (bid >= LOGITS_BLOCKS) {
        // ------------------------- fill branch -------------------------
        float4* __restrict__ out4 = (float4*)(out + IDX_OFF);
        const size_t base = (size_t)(bid - LOGITS_BLOCKS) * FILL_F4_PER_BLOCK
                          + threadIdx.x;
#pragma unroll
        for (int j = 0; j < FILL_F4_PER_THREAD; j++) {
            const size_t i = base + (size_t)j * 128;
            const float v = (float)((i >> 9) & (T_TOKENS - 1));
            __stcs(&out4[i], make_float4(v, v, v, v));
        }
        return;
    }

    // ------------------------- logits branch -------------------------
    const int warp = threadIdx.x >> 5;
    const int lane = threadIdx.x & 31;
    const int t0 = ((int)bid * 4 + warp) * TPW;      // 2 tokens per warp

    const float4* __restrict__ hs4 = (const float4*)hs;
    const float4* __restrict__ w4  = (const float4*)wr;

    float acc[TPW][N_EXP];
#pragma unroll
    for (int a = 0; a < TPW; a++)
#pragma unroll
        for (int e = 0; e < N_EXP; e++) acc[a][e] = 0.f;

#pragma unroll 2
    for (int ii = 0; ii < H4 / 32; ii++) {           // 16 iterations
        const int i = ii * 32 + lane;
        float4 x[TPW];
#pragma unroll
        for (int a = 0; a < TPW; a++)
            x[a] = hs4[(size_t)(t0 + a) * H4 + i];
#pragma unroll
        for (int e = 0; e < N_EXP; e++) {
            const float4 wv = __ldg(&w4[e * H4 + i]);
#pragma unroll
            for (int a = 0; a < TPW; a++) {
                acc[a][e] += x[a].x * wv.x + x[a].y * wv.y
                           + x[a].z * wv.z + x[a].w * wv.w;
            }
        }
    }

    // butterfly warp reduction
#pragma unroll
    for (int a = 0; a < TPW; a++)
#pragma unroll
        for (int e = 0; e < N_EXP; e++)
#pragma unroll
            for (int o = 16; o > 0; o >>= 1)
                acc[a][e] += __shfl_xor_sync(0xffffffffu, acc[a][e], o);

    if (lane == 0) {
#pragma unroll
        for (int a = 0; a < TPW; a++) {
            const int t = t0 + a;
            float b1 = -CUDART_INF_F; int i1 = 0;
#pragma unroll
            for (int e = 0; e < N_EXP; e++)
                if (acc[a][e] > b1) { b1 = acc[a][e]; i1 = e; }
            float b2 = -CUDART_INF_F; int i2 = -1;
#pragma unroll
            for (int e = 0; e < N_EXP; e++)
                if (e != i1 && acc[a][e] > b2) { b2 = acc[a][e]; i2 = e; }

            const float s1 = 1.f / (1.f + __expf(-b1));
            const float s2 = 1.f / (1.f + __expf(-b2));
#pragma unroll
            for (int e = 0; e < N_EXP; e++) {
                const float s = (e == i1) ? s1 : ((e == i2) ? s2 : 0.f);
                out[SCORES_OFF + (size_t)e * T_TOKENS + t] = s;
                out[PROBS_OFF  + (size_t)e * T_TOKENS + t] = s;
            }
        }
    }
}

extern "C" void kernel_launch(void* const* d_in, const int* in_sizes, int n_in,
                              void* d_out, int out_size) {
    const float* hs = (const float*)d_in[0];  // [T, H] fp32
    const float* wr = (const float*)d_in[1];  // [E, H] fp32
    float* out = (float*)d_out;

    router_fused_kernel<<<GRID_BLOCKS, 128>>>(hs, wr, out);
}